// round 10
// baseline (speedup 1.0000x reference)
#include <cuda_runtime.h>

// SecGELU: out = (i>=0 ? x : 0) - table[min(|i>>6|, 4095)]
// where i = rint(x * 2^16) as int32 (exact ring semantics).
//
// R7 config with 512-thread blocks: 2 straight-line tiles x 512 thr
// = 16384 elems/block, 4096 blocks. Table staged half as often as R7
// (per-block startup cost halved) with identical per-thread code, so
// registers (32) and thread-occupancy (~2048/SM) are unchanged.
//  - integer fixed-point path: F2I.RN + SHF + IABS + IMNMX
//  - 16 KB table in SMEM via cp.async.cg (no register landing)
//  - tile-0 stream loads prefetched before staging

#define SECGELU_TABLE_SIZE 4096
#define THREADS 512
#define V4_PER_THREAD 4                         // 16 elements per thread per tile
#define V4_PER_TILE (THREADS * V4_PER_THREAD)   // 2048 float4 = 8192 elems
#define TILES_PER_BLOCK 2
#define V4_PER_BLOCK (V4_PER_TILE * TILES_PER_BLOCK)  // 4096 float4 = 16384 elems

__device__ __forceinline__ float secgelu_one(float xi, const float* __restrict__ s_tab) {
    int i = __float2int_rn(xi * 65536.0f);   // X = round(x * 2^16), round-half-even
    int y = i >> 6;                          // floor division by 64 (exact for negatives)
    int a = (y >= 0) ? y : -y;               // |y|
    int c = min(a, SECGELU_TABLE_SIZE - 1);  // clamp
    float t = s_tab[c];
    return ((i >= 0) ? xi : 0.0f) - t;       // d*x - table[c]
}

__device__ __forceinline__ void secgelu_compute_store(const float4* v,
                                                      float4* __restrict__ out4,
                                                      int base,
                                                      const float* __restrict__ s_tab) {
    float4 r[V4_PER_THREAD];
    #pragma unroll
    for (int k = 0; k < V4_PER_THREAD; k++) {
        r[k].x = secgelu_one(v[k].x, s_tab);
        r[k].y = secgelu_one(v[k].y, s_tab);
        r[k].z = secgelu_one(v[k].z, s_tab);
        r[k].w = secgelu_one(v[k].w, s_tab);
    }
    #pragma unroll
    for (int k = 0; k < V4_PER_THREAD; k++)
        out4[base + k * THREADS] = r[k];
}

__global__ void __launch_bounds__(THREADS)
secgelu_main_kernel(const float4* __restrict__ x4,
                    const float4* __restrict__ table4,
                    float4* __restrict__ out4) {
    __shared__ float s_tab[SECGELU_TABLE_SIZE];

    int base = blockIdx.x * V4_PER_BLOCK + threadIdx.x;

    // Prefetch tile 0's stream loads (in flight during table staging).
    float4 v0[V4_PER_THREAD];
    #pragma unroll
    for (int k = 0; k < V4_PER_THREAD; k++)
        v0[k] = x4[base + k * THREADS];

    // Stage table via cp.async.cg: 16 bytes/thread x 2 iterations = 16 KB.
    // No register landing, no STS in the warp instruction stream.
    {
        unsigned int s_addr = (unsigned int)__cvta_generic_to_shared(s_tab)
                              + threadIdx.x * 16u;
        const float4* g = table4 + threadIdx.x;
        #pragma unroll
        for (int i = 0; i < SECGELU_TABLE_SIZE / 4 / THREADS; i++) {
            asm volatile("cp.async.cg.shared.global [%0], [%1], 16;"
                         :: "r"(s_addr + i * (THREADS * 16u)),
                            "l"(g + i * THREADS));
        }
        asm volatile("cp.async.commit_group;");
        asm volatile("cp.async.wait_group 0;" ::: "memory");
    }
    __syncthreads();

    // Tile 0 (prefetched)
    secgelu_compute_store(v0, out4, base, s_tab);

    // Remaining tiles
    #pragma unroll
    for (int t = 1; t < TILES_PER_BLOCK; t++) {
        int b = base + t * V4_PER_TILE;
        float4 v[V4_PER_THREAD];
        #pragma unroll
        for (int k = 0; k < V4_PER_THREAD; k++)
            v[k] = x4[b + k * THREADS];
        secgelu_compute_store(v, out4, b, s_tab);
    }
}

__global__ void __launch_bounds__(256)
secgelu_tail_kernel(const float* __restrict__ x,
                    const float* __restrict__ table,
                    float* __restrict__ out,
                    long long start, long long n) {
    long long i = start + (long long)blockIdx.x * 256 + threadIdx.x;
    if (i >= n) return;
    float xi = x[i];
    int ii = __float2int_rn(xi * 65536.0f);
    int y = ii >> 6;
    int a = (y >= 0) ? y : -y;
    int c = min(a, SECGELU_TABLE_SIZE - 1);
    out[i] = ((ii >= 0) ? xi : 0.0f) - table[c];
}

extern "C" void kernel_launch(void* const* d_in, const int* in_sizes, int n_in,
                              void* d_out, int out_size) {
    const float* x     = (const float*)d_in[0];
    const float* table = (const float*)d_in[1];
    float* out         = (float*)d_out;

    long long n = (long long)in_sizes[0];
    long long elems_per_block = (long long)V4_PER_BLOCK * 4;  // 65536 bytes = 16384 elems
    long long nblocks = n / elems_per_block;

    if (nblocks > 0) {
        secgelu_main_kernel<<<(int)nblocks, THREADS>>>(
            (const float4*)x, (const float4*)table, (float4*)out);
    }
    long long done = nblocks * elems_per_block;
    long long n_tail = n - done;
    if (n_tail > 0) {
        long long tblocks = (n_tail + 255) / 256;
        secgelu_tail_kernel<<<(int)tblocks, 256>>>(x, table, out, done, n);
    }
}

// round 11
// speedup vs baseline: 1.0004x; 1.0004x over previous
#include <cuda_runtime.h>

// SecGELU: out = (i>=0 ? x : 0) - table[min(|i>>6|, 4095)]
// where i = rint(x * 2^16) as int32 (exact ring semantics).
//
// FINAL (R7 config) — converged at the mixed read/write HBM ceiling
// (~6.4 TB/s, DRAM pipe ~80%, occ ~87%, issue ~29%, regs 32).
// Probed and rejected in isolation: persistent grid (R3), 4 tiles (R5),
// register prefetch (R6), .cs hints (R8), 512-thr blocks (R10).
//  - integer fixed-point path: F2I.RN + SHF + IABS + IMNMX
//    (bit-exact vs jnp.round / floor-div ring semantics)
//  - 16 KB table in SMEM, staged via cp.async.cg (no register landing)
//  - tile-0 stream loads prefetched before staging (latency overlap
//    at zero register cost)
//  - 2 tiles/block, 8192 one-shot blocks, 32-bit indices, float4 I/O

#define SECGELU_TABLE_SIZE 4096
#define THREADS 256
#define V4_PER_THREAD 4                         // 16 elements per thread per tile
#define V4_PER_TILE (THREADS * V4_PER_THREAD)   // 1024 float4 = 4096 elems
#define TILES_PER_BLOCK 2
#define V4_PER_BLOCK (V4_PER_TILE * TILES_PER_BLOCK)  // 2048 float4 = 8192 elems

__device__ __forceinline__ float secgelu_one(float xi, const float* __restrict__ s_tab) {
    int i = __float2int_rn(xi * 65536.0f);   // X = round(x * 2^16), round-half-even
    int y = i >> 6;                          // floor division by 64 (exact for negatives)
    int a = (y >= 0) ? y : -y;               // |y|
    int c = min(a, SECGELU_TABLE_SIZE - 1);  // clamp
    float t = s_tab[c];
    return ((i >= 0) ? xi : 0.0f) - t;       // d*x - table[c]
}

__device__ __forceinline__ void secgelu_compute_store(const float4* v,
                                                      float4* __restrict__ out4,
                                                      int base,
                                                      const float* __restrict__ s_tab) {
    float4 r[V4_PER_THREAD];
    #pragma unroll
    for (int k = 0; k < V4_PER_THREAD; k++) {
        r[k].x = secgelu_one(v[k].x, s_tab);
        r[k].y = secgelu_one(v[k].y, s_tab);
        r[k].z = secgelu_one(v[k].z, s_tab);
        r[k].w = secgelu_one(v[k].w, s_tab);
    }
    #pragma unroll
    for (int k = 0; k < V4_PER_THREAD; k++)
        out4[base + k * THREADS] = r[k];
}

__global__ void __launch_bounds__(THREADS)
secgelu_main_kernel(const float4* __restrict__ x4,
                    const float4* __restrict__ table4,
                    float4* __restrict__ out4) {
    __shared__ float s_tab[SECGELU_TABLE_SIZE];

    int base = blockIdx.x * V4_PER_BLOCK + threadIdx.x;

    // Prefetch tile 0's stream loads (in flight during table staging).
    float4 v0[V4_PER_THREAD];
    #pragma unroll
    for (int k = 0; k < V4_PER_THREAD; k++)
        v0[k] = x4[base + k * THREADS];

    // Stage table via cp.async.cg: 16 bytes/thread x 4 iterations = 16 KB.
    // No register landing, no STS in the warp instruction stream.
    {
        unsigned int s_addr = (unsigned int)__cvta_generic_to_shared(s_tab)
                              + threadIdx.x * 16u;
        const float4* g = table4 + threadIdx.x;
        #pragma unroll
        for (int i = 0; i < SECGELU_TABLE_SIZE / 4 / THREADS; i++) {
            asm volatile("cp.async.cg.shared.global [%0], [%1], 16;"
                         :: "r"(s_addr + i * (THREADS * 16u)),
                            "l"(g + i * THREADS));
        }
        asm volatile("cp.async.commit_group;");
        asm volatile("cp.async.wait_group 0;" ::: "memory");
    }
    __syncthreads();

    // Tile 0 (prefetched)
    secgelu_compute_store(v0, out4, base, s_tab);

    // Remaining tiles
    #pragma unroll
    for (int t = 1; t < TILES_PER_BLOCK; t++) {
        int b = base + t * V4_PER_TILE;
        float4 v[V4_PER_THREAD];
        #pragma unroll
        for (int k = 0; k < V4_PER_THREAD; k++)
            v[k] = x4[b + k * THREADS];
        secgelu_compute_store(v, out4, b, s_tab);
    }
}

__global__ void __launch_bounds__(THREADS)
secgelu_tail_kernel(const float* __restrict__ x,
                    const float* __restrict__ table,
                    float* __restrict__ out,
                    long long start, long long n) {
    long long i = start + (long long)blockIdx.x * THREADS + threadIdx.x;
    if (i >= n) return;
    float xi = x[i];
    int ii = __float2int_rn(xi * 65536.0f);
    int y = ii >> 6;
    int a = (y >= 0) ? y : -y;
    int c = min(a, SECGELU_TABLE_SIZE - 1);
    out[i] = ((ii >= 0) ? xi : 0.0f) - table[c];
}

extern "C" void kernel_launch(void* const* d_in, const int* in_sizes, int n_in,
                              void* d_out, int out_size) {
    const float* x     = (const float*)d_in[0];
    const float* table = (const float*)d_in[1];
    float* out         = (float*)d_out;

    long long n = (long long)in_sizes[0];
    long long elems_per_block = (long long)V4_PER_BLOCK * 4;  // 8192
    long long nblocks = n / elems_per_block;

    if (nblocks > 0) {
        secgelu_main_kernel<<<(int)nblocks, THREADS>>>(
            (const float4*)x, (const float4*)table, (float4*)out);
    }
    long long done = nblocks * elems_per_block;
    long long n_tail = n - done;
    if (n_tail > 0) {
        long long tblocks = (n_tail + THREADS - 1) / THREADS;
        secgelu_tail_kernel<<<(int)tblocks, THREADS>>>(x, table, out, done, n);
    }
}

// round 12
// speedup vs baseline: 1.0055x; 1.0051x over previous
#include <cuda_runtime.h>

// SecGELU: out = (i>=0 ? x : 0) - table[min(|i>>6|, 4095)]
// where i = rint(x * 2^16) as int32 (exact ring semantics).
//
// Final probe: R2 grid shape (1 tile/block, 16384 one-shot blocks --
// finest CTA granularity, best wave balance) combined with R7's
// zero-register staging (cp.async.cg) + tile-0 prefetch. Staging L2
// reads double vs R7 but are L2-hits (no DRAM impact, verified R4->R7).
//  - integer fixed-point path: F2I.RN + SHF + IABS + IMNMX
//  - 16 KB table in SMEM via cp.async.cg (no register landing)
//  - float4 I/O, 32-bit indices, regs 32

#define SECGELU_TABLE_SIZE 4096
#define THREADS 256
#define V4_PER_THREAD 4                         // 16 elements per thread
#define V4_PER_BLOCK (THREADS * V4_PER_THREAD)  // 1024 float4 = 4096 elems

__device__ __forceinline__ float secgelu_one(float xi, const float* __restrict__ s_tab) {
    int i = __float2int_rn(xi * 65536.0f);   // X = round(x * 2^16), round-half-even
    int y = i >> 6;                          // floor division by 64 (exact for negatives)
    int a = (y >= 0) ? y : -y;               // |y|
    int c = min(a, SECGELU_TABLE_SIZE - 1);  // clamp
    float t = s_tab[c];
    return ((i >= 0) ? xi : 0.0f) - t;       // d*x - table[c]
}

__global__ void __launch_bounds__(THREADS)
secgelu_main_kernel(const float4* __restrict__ x4,
                    const float4* __restrict__ table4,
                    float4* __restrict__ out4) {
    __shared__ float s_tab[SECGELU_TABLE_SIZE];

    int base = blockIdx.x * V4_PER_BLOCK + threadIdx.x;

    // Prefetch the tile's stream loads (in flight during table staging).
    float4 v[V4_PER_THREAD];
    #pragma unroll
    for (int k = 0; k < V4_PER_THREAD; k++)
        v[k] = x4[base + k * THREADS];

    // Stage table via cp.async.cg: 16 bytes/thread x 4 iterations = 16 KB.
    // No register landing, no STS in the warp instruction stream.
    {
        unsigned int s_addr = (unsigned int)__cvta_generic_to_shared(s_tab)
                              + threadIdx.x * 16u;
        const float4* g = table4 + threadIdx.x;
        #pragma unroll
        for (int i = 0; i < SECGELU_TABLE_SIZE / 4 / THREADS; i++) {
            asm volatile("cp.async.cg.shared.global [%0], [%1], 16;"
                         :: "r"(s_addr + i * (THREADS * 16u)),
                            "l"(g + i * THREADS));
        }
        asm volatile("cp.async.commit_group;");
        asm volatile("cp.async.wait_group 0;" ::: "memory");
    }
    __syncthreads();

    float4 r[V4_PER_THREAD];
    #pragma unroll
    for (int k = 0; k < V4_PER_THREAD; k++) {
        r[k].x = secgelu_one(v[k].x, s_tab);
        r[k].y = secgelu_one(v[k].y, s_tab);
        r[k].z = secgelu_one(v[k].z, s_tab);
        r[k].w = secgelu_one(v[k].w, s_tab);
    }
    #pragma unroll
    for (int k = 0; k < V4_PER_THREAD; k++)
        out4[base + k * THREADS] = r[k];
}

__global__ void __launch_bounds__(THREADS)
secgelu_tail_kernel(const float* __restrict__ x,
                    const float* __restrict__ table,
                    float* __restrict__ out,
                    long long start, long long n) {
    long long i = start + (long long)blockIdx.x * THREADS + threadIdx.x;
    if (i >= n) return;
    float xi = x[i];
    int ii = __float2int_rn(xi * 65536.0f);
    int y = ii >> 6;
    int a = (y >= 0) ? y : -y;
    int c = min(a, SECGELU_TABLE_SIZE - 1);
    out[i] = ((ii >= 0) ? xi : 0.0f) - table[c];
}

extern "C" void kernel_launch(void* const* d_in, const int* in_sizes, int n_in,
                              void* d_out, int out_size) {
    const float* x     = (const float*)d_in[0];
    const float* table = (const float*)d_in[1];
    float* out         = (float*)d_out;

    long long n = (long long)in_sizes[0];
    long long elems_per_block = (long long)V4_PER_BLOCK * 4;  // 4096
    long long nblocks = n / elems_per_block;

    if (nblocks > 0) {
        secgelu_main_kernel<<<(int)nblocks, THREADS>>>(
            (const float4*)x, (const float4*)table, (float4*)out);
    }
    long long done = nblocks * elems_per_block;
    long long n_tail = n - done;
    if (n_tail > 0) {
        long long tblocks = (n_tail + THREADS - 1) / THREADS;
        secgelu_tail_kernel<<<(int)tblocks, THREADS>>>(x, table, out, done, n);
    }
}

// round 13
// speedup vs baseline: 1.0142x; 1.0087x over previous
#include <cuda_runtime.h>

// SecGELU: out = (i>=0 ? x : 0) - table[min(|i>>6|, 4095)]
// where i = rint(x * 2^16) as int32 (exact ring semantics).
//
// Granularity probe: V4_PER_THREAD=2 -> 2048 elems/block, 32768 one-shot
// blocks (finest point on the monotone granularity gradient
// 4096->8192->16384 blocks = 76.8->75.8->75.4 us). cp.async staging +
// prefetch unchanged from R12.
//  - integer fixed-point path: F2I.RN + SHF + IABS + IMNMX
//  - 16 KB table in SMEM via cp.async.cg (no register landing)
//  - float4 I/O, 32-bit indices

#define SECGELU_TABLE_SIZE 4096
#define THREADS 256
#define V4_PER_THREAD 2                         // 8 elements per thread
#define V4_PER_BLOCK (THREADS * V4_PER_THREAD)  // 512 float4 = 2048 elems

__device__ __forceinline__ float secgelu_one(float xi, const float* __restrict__ s_tab) {
    int i = __float2int_rn(xi * 65536.0f);   // X = round(x * 2^16), round-half-even
    int y = i >> 6;                          // floor division by 64 (exact for negatives)
    int a = (y >= 0) ? y : -y;               // |y|
    int c = min(a, SECGELU_TABLE_SIZE - 1);  // clamp
    float t = s_tab[c];
    return ((i >= 0) ? xi : 0.0f) - t;       // d*x - table[c]
}

__global__ void __launch_bounds__(THREADS)
secgelu_main_kernel(const float4* __restrict__ x4,
                    const float4* __restrict__ table4,
                    float4* __restrict__ out4) {
    __shared__ float s_tab[SECGELU_TABLE_SIZE];

    int base = blockIdx.x * V4_PER_BLOCK + threadIdx.x;

    // Prefetch the tile's stream loads (in flight during table staging).
    float4 v[V4_PER_THREAD];
    #pragma unroll
    for (int k = 0; k < V4_PER_THREAD; k++)
        v[k] = x4[base + k * THREADS];

    // Stage table via cp.async.cg: 16 bytes/thread x 4 iterations = 16 KB.
    // No register landing, no STS in the warp instruction stream.
    {
        unsigned int s_addr = (unsigned int)__cvta_generic_to_shared(s_tab)
                              + threadIdx.x * 16u;
        const float4* g = table4 + threadIdx.x;
        #pragma unroll
        for (int i = 0; i < SECGELU_TABLE_SIZE / 4 / THREADS; i++) {
            asm volatile("cp.async.cg.shared.global [%0], [%1], 16;"
                         :: "r"(s_addr + i * (THREADS * 16u)),
                            "l"(g + i * THREADS));
        }
        asm volatile("cp.async.commit_group;");
        asm volatile("cp.async.wait_group 0;" ::: "memory");
    }
    __syncthreads();

    float4 r[V4_PER_THREAD];
    #pragma unroll
    for (int k = 0; k < V4_PER_THREAD; k++) {
        r[k].x = secgelu_one(v[k].x, s_tab);
        r[k].y = secgelu_one(v[k].y, s_tab);
        r[k].z = secgelu_one(v[k].z, s_tab);
        r[k].w = secgelu_one(v[k].w, s_tab);
    }
    #pragma unroll
    for (int k = 0; k < V4_PER_THREAD; k++)
        out4[base + k * THREADS] = r[k];
}

__global__ void __launch_bounds__(THREADS)
secgelu_tail_kernel(const float* __restrict__ x,
                    const float* __restrict__ table,
                    float* __restrict__ out,
                    long long start, long long n) {
    long long i = start + (long long)blockIdx.x * THREADS + threadIdx.x;
    if (i >= n) return;
    float xi = x[i];
    int ii = __float2int_rn(xi * 65536.0f);
    int y = ii >> 6;
    int a = (y >= 0) ? y : -y;
    int c = min(a, SECGELU_TABLE_SIZE - 1);
    out[i] = ((ii >= 0) ? xi : 0.0f) - table[c];
}

extern "C" void kernel_launch(void* const* d_in, const int* in_sizes, int n_in,
                              void* d_out, int out_size) {
    const float* x     = (const float*)d_in[0];
    const float* table = (const float*)d_in[1];
    float* out         = (float*)d_out;

    long long n = (long long)in_sizes[0];
    long long elems_per_block = (long long)V4_PER_BLOCK * 4;  // 2048
    long long nblocks = n / elems_per_block;

    if (nblocks > 0) {
        secgelu_main_kernel<<<(int)nblocks, THREADS>>>(
            (const float4*)x, (const float4*)table, (float4*)out);
    }
    long long done = nblocks * elems_per_block;
    long long n_tail = n - done;
    if (n_tail > 0) {
        long long tblocks = (n_tail + THREADS - 1) / THREADS;
        secgelu_tail_kernel<<<(int)tblocks, THREADS>>>(x, table, out, done, n);
    }
}